// round 16
// baseline (speedup 1.0000x reference)
#include <cuda_runtime.h>
#include <cuda_fp16.h>
#include <stdint.h>

#define BB 8
#define TT 4096
#define NI 64
#define DD 128
#define OO 64
#define NT (BB*TT)          // 32768 rows
#define SEG 32
#define NSEG (NT/SEG)       // 1024 segments

// ------------------------- scratch (device globals) -------------------------
__device__ float g_hbar[NT*DD];
__device__ float g_z[NT*DD];
__device__ float g_seg[NSEG*DD];
__device__ uint4 g_bf1h[32*16*32];  // stage1 h-col frags: [K=32][ntg=16][lane=32] {hi0,hi1,lo0,lo1}
__device__ uint2 g_bf1z[32*16*32];  // stage1 z-col frags, HI only
__device__ uint2 g_bf3h[64*8*32];   // stage3 B frags, HI only: [chunk=64][ntg=8][lane=32]

// ------------------------- helpers -------------------------
static __device__ __forceinline__ float clip7(float x){
  return fminf(fmaxf((x + 1.0f) * 3.5f, 0.0f), 7.0f);
}
static __device__ __forceinline__ float hatf(float t, float p){
  return fmaxf(0.0f, 1.0f - fabsf(t - p));
}
static __device__ __forceinline__ void pack_hl(float a, float b, uint32_t& hi, uint32_t& lo){
  __half2 h = __floats2half2_rn(a, b);
  float2  f = __half22float2(h);
  __half2 l = __floats2half2_rn(a - f.x, b - f.y);
  hi = *reinterpret_cast<uint32_t*>(&h);
  lo = *reinterpret_cast<uint32_t*>(&l);
}
static __device__ __forceinline__ uint32_t pack_h(float a, float b){
  __half2 h = __floats2half2_rn(a, b);
  return *reinterpret_cast<uint32_t*>(&h);
}
static __device__ __forceinline__ void mma16816(float* c, const uint32_t* a, uint32_t b0, uint32_t b1){
  asm volatile(
    "mma.sync.aligned.m16n8k16.row.col.f32.f16.f16.f32 "
    "{%0,%1,%2,%3}, {%4,%5,%6,%7}, {%8,%9}, {%0,%1,%2,%3};"
    : "+f"(c[0]), "+f"(c[1]), "+f"(c[2]), "+f"(c[3])
    : "r"(a[0]), "r"(a[1]), "r"(a[2]), "r"(a[3]), "r"(b0), "r"(b1));
}
static __device__ __forceinline__ uint32_t smem_u32(const void* p){
  uint32_t a;
  asm("{ .reg .u64 t; cvta.to.shared.u64 t, %1; cvt.u32.u64 %0, t; }" : "=r"(a) : "l"(p));
  return a;
}
static __device__ __forceinline__ void cpa16(uint32_t sa, const void* g){
  asm volatile("cp.async.cg.shared.global [%0], [%1], 16;" :: "r"(sa), "l"(g));
}
#define CPA_COMMIT()  asm volatile("cp.async.commit_group;" ::: "memory")
#define CPA_WAIT1()   asm volatile("cp.async.wait_group 1;" ::: "memory")

// ------------------------- k0: build fragment-major B tables (x16 scale) -------------------------
__global__ void k0_prep(const float* __restrict__ zv, const float* __restrict__ hv,
                        const float* __restrict__ ov){
  int t = blockIdx.x * blockDim.x + threadIdx.x;
  if (t < 16384){                       // g_bf1h: h table (hi+lo)
    int lane = t & 31, ntg = (t >> 5) & 15, K = t >> 9;
    int q = lane & 3, g = lane >> 2;
    int n  = ntg * 8 + g;               // 0..127
    int kr = q * 2;
    int i0 = 2 * K;
    float v0 = hv[((i0    )*8 + kr    )*128 + n] * 16.0f;
    float v1 = hv[((i0    )*8 + kr + 1)*128 + n] * 16.0f;
    float v2 = hv[((i0 + 1)*8 + kr    )*128 + n] * 16.0f;
    float v3 = hv[((i0 + 1)*8 + kr + 1)*128 + n] * 16.0f;
    uint4 o;
    pack_hl(v0, v1, o.x, o.z);
    pack_hl(v2, v3, o.y, o.w);
    g_bf1h[t] = o;
  } else if (t < 32768){                // g_bf1z: z table (hi only)
    int e = t - 16384;
    int lane = e & 31, ntg = (e >> 5) & 15, K = e >> 9;
    int q = lane & 3, g = lane >> 2;
    int n  = ntg * 8 + g;
    int kr = q * 2;
    int i0 = 2 * K;
    float v0 = zv[((i0    )*8 + kr    )*128 + n] * 16.0f;
    float v1 = zv[((i0    )*8 + kr + 1)*128 + n] * 16.0f;
    float v2 = zv[((i0 + 1)*8 + kr    )*128 + n] * 16.0f;
    float v3 = zv[((i0 + 1)*8 + kr + 1)*128 + n] * 16.0f;
    g_bf1z[e] = make_uint2(pack_h(v0, v1), pack_h(v2, v3));
  } else if (t < 32768 + 16384){        // g_bf3h
    int e = t - 32768;
    int lane = e & 31, ntg = (e >> 5) & 7, K = e >> 8;
    int q = lane & 3, g = lane >> 2;
    int n  = ntg * 8 + g;
    int kr = q * 2;
    int i0 = 2 * K;
    float v0 = ov[((i0    )*8 + kr    )*64 + n] * 16.0f;
    float v1 = ov[((i0    )*8 + kr + 1)*64 + n] * 16.0f;
    float v2 = ov[((i0 + 1)*8 + kr    )*64 + n] * 16.0f;
    float v3 = ov[((i0 + 1)*8 + kr + 1)*64 + n] * 16.0f;
    g_bf3h[e] = make_uint2(pack_h(v0, v1), pack_h(v2, v3));
  }
}

// ------------------------- K1: stage-1 HMMA GEMM (h_bar 2-pass full-B + z 1-pass) -------------------------
// Software-pipelined A-build: A(K+1) built AFTER MMAs(K) are issued -> ALU overlaps tensor.
// CTA: 128 thr = 4 warps; warp (mr, nc): mr -> 32 rows; 64 h-cols + 64 z-cols per warp.
// M/CTA=64 -> grid 512. smem: t_s 64x66 f32 (16896B) + ring 3 x 12288 = 53760B (4 CTAs/SM).
#define SW1 66
#define K1_RING (64 * SW1 * 4)
__global__ void __launch_bounds__(128) k1_mma(const float* __restrict__ x){
  extern __shared__ char smraw[];
  float* t_s = (float*)smraw;
  const uint32_t bbase = smem_u32(smraw + K1_RING);

  const int tid = threadIdx.x;
  const int n0  = blockIdx.x * 64;

  #pragma unroll
  for (int s = 0; s < 2; ++s){
    uint32_t sb = bbase + (uint32_t)s * 12288u;
    #pragma unroll
    for (int j = 0; j < 4; ++j){
      int e = tid + j * 128;
      cpa16(sb + (uint32_t)e * 16u, g_bf1h + (size_t)s * 512 + e);
    }
    #pragma unroll
    for (int j = 0; j < 2; ++j){
      int e = tid + j * 128;
      cpa16(sb + 8192u + (uint32_t)e * 16u, (const uint4*)g_bf1z + (size_t)s * 256 + e);
    }
    CPA_COMMIT();
  }

  #pragma unroll
  for (int e = tid; e < 64 * 16; e += 128){
    int r = e >> 4, c4 = e & 15;
    float4 v = ((const float4*)(x + (size_t)(n0 + r) * NI))[c4];
    float* d = &t_s[r * SW1 + c4 * 4];
    d[0] = clip7(v.x); d[1] = clip7(v.y); d[2] = clip7(v.z); d[3] = clip7(v.w);
  }
  __syncthreads();

  const int w = tid >> 5, lane = tid & 31;
  const int mr = w & 1, nc = w >> 1;
  const int rowbase = mr * 32;
  const int q = lane & 3, g = lane >> 2;
  const float p0 = (float)(2 * q);

  float acc[2][16][4];
  #pragma unroll
  for (int a = 0; a < 2; ++a)
    #pragma unroll
    for (int b = 0; b < 16; ++b)
      #pragma unroll
      for (int c = 0; c < 4; ++c) acc[a][b][c] = 0.0f;

  // prologue A-build for K=0
  uint32_t ah[2][4];
  #pragma unroll
  for (int mt = 0; mt < 2; ++mt){
    int r0 = rowbase + mt * 16 + g;
    float2 tA = *(const float2*)&t_s[ r0      * SW1];
    float2 tB = *(const float2*)&t_s[(r0 + 8) * SW1];
    ah[mt][0] = pack_h(hatf(tA.x, p0), hatf(tA.x, p0 + 1.0f));
    ah[mt][1] = pack_h(hatf(tB.x, p0), hatf(tB.x, p0 + 1.0f));
    ah[mt][2] = pack_h(hatf(tA.y, p0), hatf(tA.y, p0 + 1.0f));
    ah[mt][3] = pack_h(hatf(tB.y, p0), hatf(tB.y, p0 + 1.0f));
  }

  #pragma unroll 1
  for (int K = 0; K < 32; ++K){
    CPA_WAIT1();
    __syncthreads();

    if (K + 2 < 32){
      int s = (K + 2) % 3;
      uint32_t sb = bbase + (uint32_t)s * 12288u;
      #pragma unroll
      for (int j = 0; j < 4; ++j){
        int e = tid + j * 128;
        cpa16(sb + (uint32_t)e * 16u, g_bf1h + (size_t)(K + 2) * 512 + e);
      }
      #pragma unroll
      for (int j = 0; j < 2; ++j){
        int e = tid + j * 128;
        cpa16(sb + 8192u + (uint32_t)e * 16u, (const uint4*)g_bf1z + (size_t)(K + 2) * 256 + e);
      }
      CPA_COMMIT();
    }

    const char* sp = smraw + K1_RING + (K % 3) * 12288;
    const uint4* bsh = (const uint4*)sp + (nc * 8) * 32 + lane;
    const uint2* bsz = (const uint2*)(sp + 8192) + (nc * 8) * 32 + lane;
    #pragma unroll
    for (int nt = 0; nt < 8; ++nt){
      uint4 bv = bsh[nt * 32];
      #pragma unroll
      for (int mt = 0; mt < 2; ++mt){
        mma16816(acc[mt][nt], ah[mt], bv.x, bv.y);   // Ah*Bh
        mma16816(acc[mt][nt], ah[mt], bv.z, bv.w);   // Ah*Bl (full-precision B)
      }
      uint2 bz = bsz[nt * 32];
      #pragma unroll
      for (int mt = 0; mt < 2; ++mt)
        mma16816(acc[mt][nt + 8], ah[mt], bz.x, bz.y);  // z: Ah*Bh only
    }

    // build A(K+1) while the MMAs above drain through the tensor pipe
    if (K + 1 < 32){
      const int i1 = 2 * (K + 1);
      #pragma unroll
      for (int mt = 0; mt < 2; ++mt){
        int r0 = rowbase + mt * 16 + g;
        float2 tA = *(const float2*)&t_s[ r0      * SW1 + i1];
        float2 tB = *(const float2*)&t_s[(r0 + 8) * SW1 + i1];
        ah[mt][0] = pack_h(hatf(tA.x, p0), hatf(tA.x, p0 + 1.0f));
        ah[mt][1] = pack_h(hatf(tB.x, p0), hatf(tB.x, p0 + 1.0f));
        ah[mt][2] = pack_h(hatf(tA.y, p0), hatf(tA.y, p0 + 1.0f));
        ah[mt][3] = pack_h(hatf(tB.y, p0), hatf(tB.y, p0 + 1.0f));
      }
    }
  }

  const float sc = 0.0625f;
  const int sgi = blockIdx.x * 2 + mr;
  #pragma unroll
  for (int nt = 0; nt < 8; ++nt){
    const int col = nc * 64 + nt * 8 + q * 2;
    float s0 = 0.0f, s1 = 0.0f;
    #pragma unroll
    for (int mt = 0; mt < 2; ++mt){
      float c0 = acc[mt][nt][0] * sc, c1 = acc[mt][nt][1] * sc;
      float c2 = acc[mt][nt][2] * sc, c3 = acc[mt][nt][3] * sc;
      int rg = n0 + rowbase + mt * 16 + g;
      *(float2*)&g_hbar[(size_t) rg      * DD + col] = make_float2(c0, c1);
      *(float2*)&g_hbar[(size_t)(rg + 8) * DD + col] = make_float2(c2, c3);
      s0 += c0 + c2; s1 += c1 + c3;
      float z0 = acc[mt][nt + 8][0] * sc, z1 = acc[mt][nt + 8][1] * sc;
      float z2 = acc[mt][nt + 8][2] * sc, z3 = acc[mt][nt + 8][3] * sc;
      z0 = 1.0f / (1.0f + __expf(-z0)); z1 = 1.0f / (1.0f + __expf(-z1));
      z2 = 1.0f / (1.0f + __expf(-z2)); z3 = 1.0f / (1.0f + __expf(-z3));
      *(float2*)&g_z[(size_t) rg      * DD + col] = make_float2(z0, z1);
      *(float2*)&g_z[(size_t)(rg + 8) * DD + col] = make_float2(z2, z3);
    }
    #pragma unroll
    for (int off = 4; off < 32; off <<= 1){
      s0 += __shfl_xor_sync(0xFFFFFFFFu, s0, off);
      s1 += __shfl_xor_sync(0xFFFFFFFFu, s1, off);
    }
    if (g == 0)
      *(float2*)&g_seg[(size_t)sgi * DD + col] = make_float2(s0, s1);
  }
}

// ------------------------- k2b: exclusive scan over segments (per batch) -------------------------
__global__ void k2b_scan(const float* __restrict__ h0){
  int b = blockIdx.x, d = threadIdx.x;
  float run = h0[b * DD + d];
  float* p = g_seg + (size_t)b * (TT / SEG) * DD + d;
  #pragma unroll 1
  for (int gq = 0; gq < (TT / SEG) / 16; ++gq){
    float v[16];
    #pragma unroll
    for (int j = 0; j < 16; ++j) v[j] = p[(gq * 16 + j) * DD];
    #pragma unroll
    for (int j = 0; j < 16; ++j){ float t = v[j]; p[(gq * 16 + j) * DD] = run; run += t; }
  }
}

// ------------------------- K3: fused scan-combine + stage-3 HMMA GEMM (y), 1-pass -------------------------
// M/CTA=64 -> grid 512 (per-warp work halved, balance 3.46 CTAs/SM). No smem B ring, no
// mainloop barriers; B register-double-buffered via LDG (g_bf3h L2-resident).
// CTA: 128 thr = 4 warps; warp mr -> 16 rows. smem: t3_s 64x132 f32 (33792B).
#define SW3 132
__global__ void __launch_bounds__(128) k3_mma(float* __restrict__ out_ht,
                                              float* __restrict__ y){
  extern __shared__ char smraw[];
  float* t3_s = (float*)smraw;

  const int tid = threadIdx.x;
  const int n0  = blockIdx.x * 64;

  // fused prepass (replaces k2c): this CTA's 2 segments, interleaved for 2x MLP
  {
    const int d = tid;
    float cA = g_seg[(size_t)(blockIdx.x * 2    ) * DD + d];
    float cB = g_seg[(size_t)(blockIdx.x * 2 + 1) * DD + d];
    const size_t baseA = (size_t)n0 * DD + d;
    const size_t baseB = ((size_t)n0 + 32) * DD + d;
    #pragma unroll 1
    for (int t0 = 0; t0 < 32; t0 += 8){
      float hbA[8], zzA[8], hbB[8], zzB[8];
      #pragma unroll
      for (int j = 0; j < 8; ++j){
        hbA[j] = g_hbar[baseA + (size_t)(t0 + j) * DD];
        hbB[j] = g_hbar[baseB + (size_t)(t0 + j) * DD];
        zzA[j] = g_z  [baseA + (size_t)(t0 + j) * DD];
        zzB[j] = g_z  [baseB + (size_t)(t0 + j) * DD];
      }
      #pragma unroll
      for (int j = 0; j < 8; ++j){
        cA += hbA[j];
        float hvA = fmaf(zzA[j], hbA[j] - cA, cA);
        out_ht[baseA + (size_t)(t0 + j) * DD] = hvA;
        t3_s[(t0 + j) * SW3 + d] = clip7(hvA);
        cB += hbB[j];
        float hvB = fmaf(zzB[j], hbB[j] - cB, cB);
        out_ht[baseB + (size_t)(t0 + j) * DD] = hvB;
        t3_s[(32 + t0 + j) * SW3 + d] = clip7(hvB);
      }
    }
  }
  __syncthreads();   // the ONLY barrier

  const int mr = tid >> 5, lane = tid & 31;
  const int rowbase = mr * 16;
  const int q = lane & 3, g = lane >> 2;
  const float p0 = (float)(2 * q);

  float acc[8][4];
  #pragma unroll
  for (int b = 0; b < 8; ++b)
    #pragma unroll
    for (int c = 0; c < 4; ++c) acc[b][c] = 0.0f;

  const uint2* bgl = g_bf3h + lane;
  uint2 bv[16];
  #pragma unroll
  for (int nt = 0; nt < 8; ++nt){
    bv[nt]     = __ldg(bgl + (size_t)nt * 32);            // chunk 0
    bv[nt + 8] = __ldg(bgl + (size_t)(256 + nt * 32));    // chunk 1
  }

  #pragma unroll 1
  for (int S = 0; S < 32; ++S){
    uint2 nb[16];
    if (S + 1 < 32){
      const uint2* bs = bgl + (size_t)(S + 1) * 512;
      #pragma unroll
      for (int nt = 0; nt < 8; ++nt){
        nb[nt]     = __ldg(bs + (size_t)nt * 32);
        nb[nt + 8] = __ldg(bs + (size_t)(256 + nt * 32));
      }
    }

    const int colf = S * 4;
    uint32_t ah0[4], ah1[4];
    {
      int r0 = rowbase + g;
      float4 tA = *(const float4*)&t3_s[ r0      * SW3 + colf];
      float4 tB = *(const float4*)&t3_s[(r0 + 8) * SW3 + colf];
      ah0[0] = pack_h(hatf(tA.x, p0), hatf(tA.x, p0 + 1.0f));
      ah0[1] = pack_h(hatf(tB.x, p0), hatf(tB.x, p0 + 1.0f));
      ah0[2] = pack_h(hatf(tA.y, p0), hatf(tA.y, p0 + 1.0f));
      ah0[3] = pack_h(hatf(tB.y, p0), hatf(tB.y, p0 + 1.0f));
      ah1[0] = pack_h(hatf(tA.z, p0), hatf(tA.z, p0 + 1.0f));
      ah1[1] = pack_h(hatf(tB.z, p0), hatf(tB.z, p0 + 1.0f));
      ah1[2] = pack_h(hatf(tA.w, p0), hatf(tA.w, p0 + 1.0f));
      ah1[3] = pack_h(hatf(tB.w, p0), hatf(tB.w, p0 + 1.0f));
    }

    #pragma unroll
    for (int nt = 0; nt < 8; ++nt){
      mma16816(acc[nt], ah0, bv[nt].x,     bv[nt].y);      // K=2S
      mma16816(acc[nt], ah1, bv[nt + 8].x, bv[nt + 8].y);  // K=2S+1
    }

    if (S + 1 < 32){
      #pragma unroll
      for (int j = 0; j < 16; ++j) bv[j] = nb[j];
    }
  }

  const float sc = 0.0625f;
  #pragma unroll
  for (int nt = 0; nt < 8; ++nt){
    const int col = nt * 8 + q * 2;
    int rg = n0 + rowbase + g;
    *(float2*)&y[(size_t) rg      * OO + col] = make_float2(acc[nt][0] * sc, acc[nt][1] * sc);
    *(float2*)&y[(size_t)(rg + 8) * OO + col] = make_float2(acc[nt][2] * sc, acc[nt][3] * sc);
  }
}

// ------------------------- host -------------------------
extern "C" void kernel_launch(void* const* d_in, const int* in_sizes, int n_in,
                              void* d_out, int out_size) {
  const float* x  = (const float*)d_in[0];   // (B,T,I)
  const float* h0 = (const float*)d_in[1];   // (B,D)
  const float* zv = (const float*)d_in[2];   // (I,P,D)
  const float* hv = (const float*)d_in[3];   // (I,P,D)
  const float* ov = (const float*)d_in[4];   // (D,P,O)

  float* y  = (float*)d_out;                     // (B,T,O)
  float* ht = (float*)d_out + (size_t)NT * OO;   // (B,T,D)

  const int smem1 = K1_RING + 3 * 12288;   // 53760
  const int smem3 = 64 * SW3 * 4;          // 33792
  cudaFuncSetAttribute(k1_mma, cudaFuncAttributeMaxDynamicSharedMemorySize, smem1);
  cudaFuncSetAttribute(k3_mma, cudaFuncAttributeMaxDynamicSharedMemorySize, smem3);

  k0_prep<<<192, 256>>>(zv, hv, ov);
  k1_mma<<<512, 128, smem1>>>(x);
  k2b_scan<<<BB, DD>>>(h0);
  k3_mma<<<512, 128, smem3>>>(ht, y);
}

// round 17
// speedup vs baseline: 1.0448x; 1.0448x over previous
#include <cuda_runtime.h>
#include <cuda_fp16.h>
#include <stdint.h>

#define BB 8
#define TT 4096
#define NI 64
#define DD 128
#define OO 64
#define NT (BB*TT)          // 32768 rows
#define SEG 32
#define NSEG (NT/SEG)       // 1024 segments

// ------------------------- scratch (device globals) -------------------------
__device__ float g_hbar[NT*DD];
__device__ float g_z[NT*DD];
__device__ float g_seg[NSEG*DD];
__device__ uint4 g_bf1h[32*16*32];  // stage1 h-col frags: [K=32][ntg=16][lane=32] {hi0,hi1,lo0,lo1}
__device__ uint2 g_bf1z[32*16*32];  // stage1 z-col frags, HI only
__device__ uint2 g_bf3h[64*8*32];   // stage3 B frags, HI only: [chunk=64][ntg=8][lane=32]

// ------------------------- helpers -------------------------
static __device__ __forceinline__ float clip7(float x){
  return fminf(fmaxf((x + 1.0f) * 3.5f, 0.0f), 7.0f);
}
static __device__ __forceinline__ float hatf(float t, float p){
  return fmaxf(0.0f, 1.0f - fabsf(t - p));
}
static __device__ __forceinline__ void pack_hl(float a, float b, uint32_t& hi, uint32_t& lo){
  __half2 h = __floats2half2_rn(a, b);
  float2  f = __half22float2(h);
  __half2 l = __floats2half2_rn(a - f.x, b - f.y);
  hi = *reinterpret_cast<uint32_t*>(&h);
  lo = *reinterpret_cast<uint32_t*>(&l);
}
static __device__ __forceinline__ uint32_t pack_h(float a, float b){
  __half2 h = __floats2half2_rn(a, b);
  return *reinterpret_cast<uint32_t*>(&h);
}
static __device__ __forceinline__ void mma16816(float* c, const uint32_t* a, uint32_t b0, uint32_t b1){
  asm volatile(
    "mma.sync.aligned.m16n8k16.row.col.f32.f16.f16.f32 "
    "{%0,%1,%2,%3}, {%4,%5,%6,%7}, {%8,%9}, {%0,%1,%2,%3};"
    : "+f"(c[0]), "+f"(c[1]), "+f"(c[2]), "+f"(c[3])
    : "r"(a[0]), "r"(a[1]), "r"(a[2]), "r"(a[3]), "r"(b0), "r"(b1));
}
static __device__ __forceinline__ uint32_t smem_u32(const void* p){
  uint32_t a;
  asm("{ .reg .u64 t; cvta.to.shared.u64 t, %1; cvt.u32.u64 %0, t; }" : "=r"(a) : "l"(p));
  return a;
}
static __device__ __forceinline__ void cpa16(uint32_t sa, const void* g){
  asm volatile("cp.async.cg.shared.global [%0], [%1], 16;" :: "r"(sa), "l"(g));
}
#define CPA_COMMIT()  asm volatile("cp.async.commit_group;" ::: "memory")
#define CPA_WAIT1()   asm volatile("cp.async.wait_group 1;" ::: "memory")

// ------------------------- k0: build fragment-major B tables (x16 scale) -------------------------
__global__ void k0_prep(const float* __restrict__ zv, const float* __restrict__ hv,
                        const float* __restrict__ ov){
  int t = blockIdx.x * blockDim.x + threadIdx.x;
  if (t < 16384){                       // g_bf1h: h table (hi+lo)
    int lane = t & 31, ntg = (t >> 5) & 15, K = t >> 9;
    int q = lane & 3, g = lane >> 2;
    int n  = ntg * 8 + g;               // 0..127
    int kr = q * 2;
    int i0 = 2 * K;
    float v0 = hv[((i0    )*8 + kr    )*128 + n] * 16.0f;
    float v1 = hv[((i0    )*8 + kr + 1)*128 + n] * 16.0f;
    float v2 = hv[((i0 + 1)*8 + kr    )*128 + n] * 16.0f;
    float v3 = hv[((i0 + 1)*8 + kr + 1)*128 + n] * 16.0f;
    uint4 o;
    pack_hl(v0, v1, o.x, o.z);
    pack_hl(v2, v3, o.y, o.w);
    g_bf1h[t] = o;
  } else if (t < 32768){                // g_bf1z: z table (hi only)
    int e = t - 16384;
    int lane = e & 31, ntg = (e >> 5) & 15, K = e >> 9;
    int q = lane & 3, g = lane >> 2;
    int n  = ntg * 8 + g;
    int kr = q * 2;
    int i0 = 2 * K;
    float v0 = zv[((i0    )*8 + kr    )*128 + n] * 16.0f;
    float v1 = zv[((i0    )*8 + kr + 1)*128 + n] * 16.0f;
    float v2 = zv[((i0 + 1)*8 + kr    )*128 + n] * 16.0f;
    float v3 = zv[((i0 + 1)*8 + kr + 1)*128 + n] * 16.0f;
    g_bf1z[e] = make_uint2(pack_h(v0, v1), pack_h(v2, v3));
  } else if (t < 32768 + 16384){        // g_bf3h
    int e = t - 32768;
    int lane = e & 31, ntg = (e >> 5) & 7, K = e >> 8;
    int q = lane & 3, g = lane >> 2;
    int n  = ntg * 8 + g;
    int kr = q * 2;
    int i0 = 2 * K;
    float v0 = ov[((i0    )*8 + kr    )*64 + n] * 16.0f;
    float v1 = ov[((i0    )*8 + kr + 1)*64 + n] * 16.0f;
    float v2 = ov[((i0 + 1)*8 + kr    )*64 + n] * 16.0f;
    float v3 = ov[((i0 + 1)*8 + kr + 1)*64 + n] * 16.0f;
    g_bf3h[e] = make_uint2(pack_h(v0, v1), pack_h(v2, v3));
  }
}

// ------------------------- K1: stage-1 HMMA GEMM (h_bar 2-pass full-B + z 1-pass) -------------------------
// R14 form (measured best ~42us): A-build in-loop before wait; ptxas schedules the overlap.
// CTA: 128 thr = 4 warps; warp (mr, nc): mr -> 32 rows; 64 h-cols + 64 z-cols per warp.
// M/CTA=64 -> grid 512. smem: t_s 64x66 f32 (16896B) + ring 3 x 12288 = 53760B (4 CTAs/SM).
#define SW1 66
#define K1_RING (64 * SW1 * 4)
__global__ void __launch_bounds__(128) k1_mma(const float* __restrict__ x){
  extern __shared__ char smraw[];
  float* t_s = (float*)smraw;
  const uint32_t bbase = smem_u32(smraw + K1_RING);

  const int tid = threadIdx.x;
  const int n0  = blockIdx.x * 64;

  #pragma unroll
  for (int s = 0; s < 2; ++s){
    uint32_t sb = bbase + (uint32_t)s * 12288u;
    #pragma unroll
    for (int j = 0; j < 4; ++j){
      int e = tid + j * 128;
      cpa16(sb + (uint32_t)e * 16u, g_bf1h + (size_t)s * 512 + e);
    }
    #pragma unroll
    for (int j = 0; j < 2; ++j){
      int e = tid + j * 128;
      cpa16(sb + 8192u + (uint32_t)e * 16u, (const uint4*)g_bf1z + (size_t)s * 256 + e);
    }
    CPA_COMMIT();
  }

  #pragma unroll
  for (int e = tid; e < 64 * 16; e += 128){
    int r = e >> 4, c4 = e & 15;
    float4 v = ((const float4*)(x + (size_t)(n0 + r) * NI))[c4];
    float* d = &t_s[r * SW1 + c4 * 4];
    d[0] = clip7(v.x); d[1] = clip7(v.y); d[2] = clip7(v.z); d[3] = clip7(v.w);
  }
  __syncthreads();

  const int w = tid >> 5, lane = tid & 31;
  const int mr = w & 1, nc = w >> 1;
  const int rowbase = mr * 32;
  const int q = lane & 3, g = lane >> 2;
  const float p0 = (float)(2 * q);

  float acc[2][16][4];
  #pragma unroll
  for (int a = 0; a < 2; ++a)
    #pragma unroll
    for (int b = 0; b < 16; ++b)
      #pragma unroll
      for (int c = 0; c < 4; ++c) acc[a][b][c] = 0.0f;

  #pragma unroll 1
  for (int K = 0; K < 32; ++K){
    const int i0 = 2 * K;
    uint32_t ah[2][4];
    #pragma unroll
    for (int mt = 0; mt < 2; ++mt){
      int r0 = rowbase + mt * 16 + g;
      float2 tA = *(const float2*)&t_s[ r0      * SW1 + i0];
      float2 tB = *(const float2*)&t_s[(r0 + 8) * SW1 + i0];
      ah[mt][0] = pack_h(hatf(tA.x, p0), hatf(tA.x, p0 + 1.0f));
      ah[mt][1] = pack_h(hatf(tB.x, p0), hatf(tB.x, p0 + 1.0f));
      ah[mt][2] = pack_h(hatf(tA.y, p0), hatf(tA.y, p0 + 1.0f));
      ah[mt][3] = pack_h(hatf(tB.y, p0), hatf(tB.y, p0 + 1.0f));
    }

    CPA_WAIT1();
    __syncthreads();

    if (K + 2 < 32){
      int s = (K + 2) % 3;
      uint32_t sb = bbase + (uint32_t)s * 12288u;
      #pragma unroll
      for (int j = 0; j < 4; ++j){
        int e = tid + j * 128;
        cpa16(sb + (uint32_t)e * 16u, g_bf1h + (size_t)(K + 2) * 512 + e);
      }
      #pragma unroll
      for (int j = 0; j < 2; ++j){
        int e = tid + j * 128;
        cpa16(sb + 8192u + (uint32_t)e * 16u, (const uint4*)g_bf1z + (size_t)(K + 2) * 256 + e);
      }
      CPA_COMMIT();
    }

    const char* sp = smraw + K1_RING + (K % 3) * 12288;
    const uint4* bsh = (const uint4*)sp + (nc * 8) * 32 + lane;
    const uint2* bsz = (const uint2*)(sp + 8192) + (nc * 8) * 32 + lane;
    #pragma unroll
    for (int nt = 0; nt < 8; ++nt){
      uint4 bv = bsh[nt * 32];
      #pragma unroll
      for (int mt = 0; mt < 2; ++mt){
        mma16816(acc[mt][nt], ah[mt], bv.x, bv.y);   // Ah*Bh
        mma16816(acc[mt][nt], ah[mt], bv.z, bv.w);   // Ah*Bl (full-precision B)
      }
      uint2 bz = bsz[nt * 32];
      #pragma unroll
      for (int mt = 0; mt < 2; ++mt)
        mma16816(acc[mt][nt + 8], ah[mt], bz.x, bz.y);  // z: Ah*Bh only
    }
  }

  const float sc = 0.0625f;
  const int sgi = blockIdx.x * 2 + mr;
  #pragma unroll
  for (int nt = 0; nt < 8; ++nt){
    const int col = nc * 64 + nt * 8 + q * 2;
    float s0 = 0.0f, s1 = 0.0f;
    #pragma unroll
    for (int mt = 0; mt < 2; ++mt){
      float c0 = acc[mt][nt][0] * sc, c1 = acc[mt][nt][1] * sc;
      float c2 = acc[mt][nt][2] * sc, c3 = acc[mt][nt][3] * sc;
      int rg = n0 + rowbase + mt * 16 + g;
      *(float2*)&g_hbar[(size_t) rg      * DD + col] = make_float2(c0, c1);
      *(float2*)&g_hbar[(size_t)(rg + 8) * DD + col] = make_float2(c2, c3);
      s0 += c0 + c2; s1 += c1 + c3;
      float z0 = acc[mt][nt + 8][0] * sc, z1 = acc[mt][nt + 8][1] * sc;
      float z2 = acc[mt][nt + 8][2] * sc, z3 = acc[mt][nt + 8][3] * sc;
      z0 = 1.0f / (1.0f + __expf(-z0)); z1 = 1.0f / (1.0f + __expf(-z1));
      z2 = 1.0f / (1.0f + __expf(-z2)); z3 = 1.0f / (1.0f + __expf(-z3));
      *(float2*)&g_z[(size_t) rg      * DD + col] = make_float2(z0, z1);
      *(float2*)&g_z[(size_t)(rg + 8) * DD + col] = make_float2(z2, z3);
    }
    #pragma unroll
    for (int off = 4; off < 32; off <<= 1){
      s0 += __shfl_xor_sync(0xFFFFFFFFu, s0, off);
      s1 += __shfl_xor_sync(0xFFFFFFFFu, s1, off);
    }
    if (g == 0)
      *(float2*)&g_seg[(size_t)sgi * DD + col] = make_float2(s0, s1);
  }
}

// ------------------------- k2b: exclusive scan over segments (per batch) -------------------------
__global__ void k2b_scan(const float* __restrict__ h0){
  int b = blockIdx.x, d = threadIdx.x;
  float run = h0[b * DD + d];
  float* p = g_seg + (size_t)b * (TT / SEG) * DD + d;
  #pragma unroll 1
  for (int gq = 0; gq < (TT / SEG) / 16; ++gq){
    float v[16];
    #pragma unroll
    for (int j = 0; j < 16; ++j) v[j] = p[(gq * 16 + j) * DD];
    #pragma unroll
    for (int j = 0; j < 16; ++j){ float t = v[j]; p[(gq * 16 + j) * DD] = run; run += t; }
  }
}

// ------------------------- K3: fused scan-combine + stage-3 HMMA GEMM (y), 1-pass -------------------------
// R16 form (measured best 28.4us): M/CTA=64 -> grid 512; no smem B ring, no mainloop barriers;
// B register-double-buffered via LDG (g_bf3h L2-resident).
// CTA: 128 thr = 4 warps; warp mr -> 16 rows. smem: t3_s 64x132 f32 (33792B).
#define SW3 132
__global__ void __launch_bounds__(128) k3_mma(float* __restrict__ out_ht,
                                              float* __restrict__ y){
  extern __shared__ char smraw[];
  float* t3_s = (float*)smraw;

  const int tid = threadIdx.x;
  const int n0  = blockIdx.x * 64;

  // fused prepass (replaces k2c): this CTA's 2 segments, interleaved for 2x MLP
  {
    const int d = tid;
    float cA = g_seg[(size_t)(blockIdx.x * 2    ) * DD + d];
    float cB = g_seg[(size_t)(blockIdx.x * 2 + 1) * DD + d];
    const size_t baseA = (size_t)n0 * DD + d;
    const size_t baseB = ((size_t)n0 + 32) * DD + d;
    #pragma unroll 1
    for (int t0 = 0; t0 < 32; t0 += 8){
      float hbA[8], zzA[8], hbB[8], zzB[8];
      #pragma unroll
      for (int j = 0; j < 8; ++j){
        hbA[j] = g_hbar[baseA + (size_t)(t0 + j) * DD];
        hbB[j] = g_hbar[baseB + (size_t)(t0 + j) * DD];
        zzA[j] = g_z  [baseA + (size_t)(t0 + j) * DD];
        zzB[j] = g_z  [baseB + (size_t)(t0 + j) * DD];
      }
      #pragma unroll
      for (int j = 0; j < 8; ++j){
        cA += hbA[j];
        float hvA = fmaf(zzA[j], hbA[j] - cA, cA);
        out_ht[baseA + (size_t)(t0 + j) * DD] = hvA;
        t3_s[(t0 + j) * SW3 + d] = clip7(hvA);
        cB += hbB[j];
        float hvB = fmaf(zzB[j], hbB[j] - cB, cB);
        out_ht[baseB + (size_t)(t0 + j) * DD] = hvB;
        t3_s[(32 + t0 + j) * SW3 + d] = clip7(hvB);
      }
    }
  }
  __syncthreads();   // the ONLY barrier

  const int mr = tid >> 5, lane = tid & 31;
  const int rowbase = mr * 16;
  const int q = lane & 3, g = lane >> 2;
  const float p0 = (float)(2 * q);

  float acc[8][4];
  #pragma unroll
  for (int b = 0; b < 8; ++b)
    #pragma unroll
    for (int c = 0; c < 4; ++c) acc[b][c] = 0.0f;

  const uint2* bgl = g_bf3h + lane;
  uint2 bv[16];
  #pragma unroll
  for (int nt = 0; nt < 8; ++nt){
    bv[nt]     = __ldg(bgl + (size_t)nt * 32);            // chunk 0
    bv[nt + 8] = __ldg(bgl + (size_t)(256 + nt * 32));    // chunk 1
  }

  #pragma unroll 1
  for (int S = 0; S < 32; ++S){
    uint2 nb[16];
    if (S + 1 < 32){
      const uint2* bs = bgl + (size_t)(S + 1) * 512;
      #pragma unroll
      for (int nt = 0; nt < 8; ++nt){
        nb[nt]     = __ldg(bs + (size_t)nt * 32);
        nb[nt + 8] = __ldg(bs + (size_t)(256 + nt * 32));
      }
    }

    const int colf = S * 4;
    uint32_t ah0[4], ah1[4];
    {
      int r0 = rowbase + g;
      float4 tA = *(const float4*)&t3_s[ r0      * SW3 + colf];
      float4 tB = *(const float4*)&t3_s[(r0 + 8) * SW3 + colf];
      ah0[0] = pack_h(hatf(tA.x, p0), hatf(tA.x, p0 + 1.0f));
      ah0[1] = pack_h(hatf(tB.x, p0), hatf(tB.x, p0 + 1.0f));
      ah0[2] = pack_h(hatf(tA.y, p0), hatf(tA.y, p0 + 1.0f));
      ah0[3] = pack_h(hatf(tB.y, p0), hatf(tB.y, p0 + 1.0f));
      ah1[0] = pack_h(hatf(tA.z, p0), hatf(tA.z, p0 + 1.0f));
      ah1[1] = pack_h(hatf(tB.z, p0), hatf(tB.z, p0 + 1.0f));
      ah1[2] = pack_h(hatf(tA.w, p0), hatf(tA.w, p0 + 1.0f));
      ah1[3] = pack_h(hatf(tB.w, p0), hatf(tB.w, p0 + 1.0f));
    }

    #pragma unroll
    for (int nt = 0; nt < 8; ++nt){
      mma16816(acc[nt], ah0, bv[nt].x,     bv[nt].y);      // K=2S
      mma16816(acc[nt], ah1, bv[nt + 8].x, bv[nt + 8].y);  // K=2S+1
    }

    if (S + 1 < 32){
      #pragma unroll
      for (int j = 0; j < 16; ++j) bv[j] = nb[j];
    }
  }

  const float sc = 0.0625f;
  #pragma unroll
  for (int nt = 0; nt < 8; ++nt){
    const int col = nt * 8 + q * 2;
    int rg = n0 + rowbase + g;
    *(float2*)&y[(size_t) rg      * OO + col] = make_float2(acc[nt][0] * sc, acc[nt][1] * sc);
    *(float2*)&y[(size_t)(rg + 8) * OO + col] = make_float2(acc[nt][2] * sc, acc[nt][3] * sc);
  }
}

// ------------------------- host -------------------------
extern "C" void kernel_launch(void* const* d_in, const int* in_sizes, int n_in,
                              void* d_out, int out_size) {
  const float* x  = (const float*)d_in[0];   // (B,T,I)
  const float* h0 = (const float*)d_in[1];   // (B,D)
  const float* zv = (const float*)d_in[2];   // (I,P,D)
  const float* hv = (const float*)d_in[3];   // (I,P,D)
  const float* ov = (const float*)d_in[4];   // (D,P,O)

  float* y  = (float*)d_out;                     // (B,T,O)
  float* ht = (float*)d_out + (size_t)NT * OO;   // (B,T,D)

  const int smem1 = K1_RING + 3 * 12288;   // 53760
  const int smem3 = 64 * SW3 * 4;          // 33792
  cudaFuncSetAttribute(k1_mma, cudaFuncAttributeMaxDynamicSharedMemorySize, smem1);
  cudaFuncSetAttribute(k3_mma, cudaFuncAttributeMaxDynamicSharedMemorySize, smem3);

  k0_prep<<<192, 256>>>(zv, hv, ov);
  k1_mma<<<512, 128, smem1>>>(x);
  k2b_scan<<<BB, DD>>>(h0);
  k3_mma<<<512, 128, smem3>>>(ht, y);
}